// round 14
// baseline (speedup 1.0000x reference)
#include <cuda_runtime.h>
#include <cstdint>

#define DIM 128
#define HID 64
#define MAX_TISSUE 4096
#define TILE 32
#define SXS 132  // padded float stride, X tile
#define SWS 132  // padded float stride, Wc staging (tf32 bits)

// scratch: projected tissue keys (+ both biases folded in)
__device__ float g_tkb[MAX_TISSUE * HID];

// ---------------------------------------------------------------------------
// Kernel A: tkb[t][h] = bt[h] + bc[h] + sum_d Wt[h][d] * tissue[t][d]
// ---------------------------------------------------------------------------
__global__ void tissue_proj_kernel(const float* __restrict__ tissue,
                                   const float* __restrict__ Wt,
                                   const float* __restrict__ bt,
                                   const float* __restrict__ bc,
                                   int n_tissue) {
    __shared__ float st[16][DIM];
    __shared__ float swt[HID][DIM + 4];
    int tid = threadIdx.x;
    int t0 = blockIdx.x * 16;

    for (int i = tid; i < HID * (DIM / 4); i += 256) {
        int h = i >> 5, c = i & 31;
        float4 v = ((const float4*)Wt)[h * 32 + c];
        *(float4*)&swt[h][c * 4] = v;
    }
    for (int i = tid; i < 16 * 32; i += 256) {
        int r = i >> 5, c = i & 31;
        float4 v = make_float4(0.f, 0.f, 0.f, 0.f);
        if (t0 + r < n_tissue) v = ((const float4*)tissue)[(size_t)(t0 + r) * 32 + c];
        *(float4*)&st[r][c * 4] = v;
    }
    __syncthreads();

    #pragma unroll
    for (int j = 0; j < 4; j++) {
        int o = tid + j * 256;
        int tl = o >> 6, h = o & 63;
        if (t0 + tl >= n_tissue) continue;
        float acc = bt[h] + bc[h];
        #pragma unroll 8
        for (int c = 0; c < 32; c++) {
            float4 w = *(const float4*)&swt[h][c * 4];
            float4 x = *(const float4*)&st[tl][c * 4];
            acc += w.x * x.x + w.y * x.y + w.z * x.z + w.w * x.w;
        }
        g_tkb[(size_t)(t0 + tl) * HID + h] = acc;
    }
}

// ---------------------------------------------------------------------------
__device__ __forceinline__ unsigned f2tf32(float x) {
    unsigned r;
    asm("cvt.rna.tf32.f32 %0, %1;" : "=r"(r) : "f"(x));
    return r;
}
__device__ __forceinline__ float tanh_ap(float x) {
    float y;
    asm("tanh.approx.f32 %0, %1;" : "=f"(y) : "f"(x));
    return y;
}
__device__ __forceinline__ void cp_async16(void* sdst, const void* gsrc, bool pred) {
    unsigned s = (unsigned)__cvta_generic_to_shared(sdst);
    int sz = pred ? 16 : 0;
    asm volatile("cp.async.cg.shared.global [%0], [%1], 16, %2;\n"
                 :: "r"(s), "l"(gsrc), "r"(sz));
}
__device__ __forceinline__ void cp_async4(void* sdst, const void* gsrc, bool pred) {
    unsigned s = (unsigned)__cvta_generic_to_shared(sdst);
    int sz = pred ? 4 : 0;
    asm volatile("cp.async.ca.shared.global [%0], [%1], 4, %2;\n"
                 :: "r"(s), "l"(gsrc), "r"(sz));
}
__device__ __forceinline__ void cp_commit() {
    asm volatile("cp.async.commit_group;\n" ::: "memory");
}
__device__ __forceinline__ void cp_wait0() {
    asm volatile("cp.async.wait_group 0;\n" ::: "memory");
}
__device__ __forceinline__ void cp_wait1() {
    asm volatile("cp.async.wait_group 1;\n" ::: "memory");
}
__device__ __forceinline__ void ldm_x4(unsigned* r, unsigned saddr) {
    asm volatile("ldmatrix.sync.aligned.m8n8.x4.shared.b16 {%0,%1,%2,%3}, [%4];"
                 : "=r"(r[0]), "=r"(r[1]), "=r"(r[2]), "=r"(r[3])
                 : "r"(saddr));
}

extern __shared__ float smem[];

// ---------------------------------------------------------------------------
// Kernel B: persistent; 32-row tiles; 2 CTAs/SM; B register-resident;
// FULLY software-pipelined: both the X stage and the tissue-gather stage are
// issued one full iteration before consumption — zero exposed waits in
// steady state. Warp grid: 2 m-tiles x 4 n-quarters.
// ---------------------------------------------------------------------------
__global__ __launch_bounds__(256, 2)
void fuse_kernel(const float* __restrict__ cellf,
                 const float* __restrict__ tissuef,
                 const int* __restrict__ c2t,
                 const float* __restrict__ Wc,
                 const float* __restrict__ attnw,
                 float* __restrict__ out,
                 int n_cell, int ntiles) {
    float*    sx    = smem;                          // 2 X buffers, 32*132
    unsigned* swc   = (unsigned*)smem;               // ALIAS: Wc staging
    float*    stis  = smem + 2 * TILE * SXS;         // 2 tissue stages, 32*128
    int*      stid  = (int*)(stis + 2 * TILE * DIM); // 2 buffers, 32 each
    float*    spart = (float*)(stid + 2 * TILE);     // 4 * 32 partials
    float*    sattn = spart + 4 * TILE;              // 64

    int tid = threadIdx.x;
    int wid = tid >> 5, lane = tid & 31;
    int gid = lane >> 2, tig = lane & 3;
    int wm = wid & 1, wn = wid >> 1;     // 2 m-tiles x 4 n-quarters
    int m0 = wm * 16;
    int rlo = m0 + gid, rhi = m0 + gid + 8;
    int h0 = wn * 16;

    int lml = lane & 7, lmm = lane >> 3;
    unsigned sx_u = (unsigned)__cvta_generic_to_shared(sx);
    unsigned a_off = ((unsigned)((m0 + (lmm & 1) * 8 + lml) * SXS + (lmm >> 1) * 4)) * 4u;
    unsigned b_off = sx_u + ((unsigned)((h0 + lml) * SWS + lmm * 4)) * 4u;

    // ---- prologue: stage Wc tf32 (aliased), extract B fragments to regs ----
    for (int i = tid; i < 64 * 32; i += 256) {
        int r = i >> 5, c = i & 31;
        float4 v = ((const float4*)Wc)[r * 32 + c];
        uint4 w;
        w.x = f2tf32(v.x); w.y = f2tf32(v.y); w.z = f2tf32(v.z); w.w = f2tf32(v.w);
        *(uint4*)&swc[r * SWS + c * 4] = w;
    }
    if (tid < 64) sattn[tid] = attnw[tid];
    __syncthreads();

    unsigned breg[2][8][4];
    #pragma unroll
    for (int nt = 0; nt < 2; nt++)
        #pragma unroll
        for (int p = 0; p < 8; p++)
            ldm_x4(breg[nt][p],
                   b_off + (unsigned)(nt * 8 * SWS) * 4u + (unsigned)(p * 64));
    __syncthreads();          // Wc staging region reusable as X buffers

    // ---- helpers ----
    auto issue_x = [&](int t, int buf) {
        float* dst = sx + buf * TILE * SXS;
        int base = t * TILE;
        #pragma unroll
        for (int j = 0; j < 4; j++) {
            int i = tid + j * 256;
            int r = i >> 5, c = i & 31;
            int row = base + r;
            bool ok = row < n_cell;
            int rowc = ok ? row : (n_cell - 1);
            cp_async16(&dst[r * SXS + c * 4],
                       cellf + (size_t)rowc * DIM + c * 4, ok);
        }
        if (tid < TILE) {
            int row = base + tid;
            bool ok = row < n_cell;
            int rowc = ok ? row : 0;
            cp_async4(&stid[buf * TILE + tid], c2t + rowc, ok);
        }
    };
    auto issue_t = [&](int t, int buf) {   // tissue gather from stid[buf]
        float* dst = stis + buf * TILE * DIM;
        int* ids = stid + buf * TILE;
        int base = t * TILE;
        #pragma unroll
        for (int j = 0; j < 4; j++) {
            int i = tid + j * 256;
            int r = i >> 5, c = i & 31;
            bool ok = (base + r) < n_cell;
            int tt = ids[r] & (MAX_TISSUE - 1);
            cp_async16(&dst[r * DIM + c * 4],
                       tissuef + (size_t)tt * DIM + c * 4, ok);
        }
    };

    int g = gridDim.x;
    int t0 = blockIdx.x;

    // ---- pipeline fill: X(t0) → wait → T(t0), X(t0+g) ----
    if (t0 < ntiles) issue_x(t0, 0);
    cp_commit();                         // [X(t0)]
    cp_wait0();
    __syncthreads();                     // X(t0)+ids(t0) resident & visible
    if (t0 < ntiles) issue_t(t0, 0);
    cp_commit();                         // [T(t0)]
    if (t0 + g < ntiles) issue_x(t0 + g, 1);
    cp_commit();                         // [T(t0), X(t0+g)]

    int it = 0;
    for (int t = t0; t < ntiles; t += g, it++) {
        int buf = it & 1;
        int base = t * TILE;
        int* bt_ = stid + buf * TILE;
        float* bx = sx + buf * TILE * SXS;
        unsigned abase = sx_u + (unsigned)(buf * TILE * SXS) * 4u + a_off;

        // ---- 1. compute on resident X(t): tkb gather + mma + score ----
        float acc[2][4];
        {
            int tlo = bt_[rlo] & (MAX_TISSUE - 1);
            int thi = bt_[rhi] & (MAX_TISSUE - 1);
            const float2* klo = (const float2*)&g_tkb[(size_t)tlo * HID];
            const float2* khi = (const float2*)&g_tkb[(size_t)thi * HID];
            #pragma unroll
            for (int nt = 0; nt < 2; nt++) {
                float2 a = klo[wn * 8 + nt * 4 + tig];
                float2 b = khi[wn * 8 + nt * 4 + tig];
                acc[nt][0] = a.x; acc[nt][1] = a.y;
                acc[nt][2] = b.x; acc[nt][3] = b.y;
            }
        }

        #pragma unroll
        for (int p = 0; p < 8; p++) {
            unsigned a0[4], a1[4];
            ldm_x4(a0, abase + (unsigned)(p * 64));        // kk = 2p
            ldm_x4(a1, abase + (unsigned)(p * 64 + 32));   // kk = 2p+1
            #pragma unroll
            for (int nt = 0; nt < 2; nt++) {
                asm volatile(
                    "mma.sync.aligned.m16n8k8.row.col.f32.tf32.tf32.f32 "
                    "{%0,%1,%2,%3}, {%4,%5,%6,%7}, {%8,%9}, {%0,%1,%2,%3};\n"
                    : "+f"(acc[nt][0]), "+f"(acc[nt][1]),
                      "+f"(acc[nt][2]), "+f"(acc[nt][3])
                    : "r"(a0[0]), "r"(a0[1]), "r"(a0[2]), "r"(a0[3]),
                      "r"(breg[nt][p][0]), "r"(breg[nt][p][1]));
                asm volatile(
                    "mma.sync.aligned.m16n8k8.row.col.f32.tf32.tf32.f32 "
                    "{%0,%1,%2,%3}, {%4,%5,%6,%7}, {%8,%9}, {%0,%1,%2,%3};\n"
                    : "+f"(acc[nt][0]), "+f"(acc[nt][1]),
                      "+f"(acc[nt][2]), "+f"(acc[nt][3])
                    : "r"(a1[0]), "r"(a1[1]), "r"(a1[2]), "r"(a1[3]),
                      "r"(breg[nt][p][2]), "r"(breg[nt][p][3]));
            }
        }

        float p0 = 0.f, p1 = 0.f;
        #pragma unroll
        for (int nt = 0; nt < 2; nt++) {
            float aw0 = sattn[h0 + nt * 8 + tig * 2];
            float aw1 = sattn[h0 + nt * 8 + tig * 2 + 1];
            p0 += aw0 * tanh_ap(acc[nt][0]) + aw1 * tanh_ap(acc[nt][1]);
            p1 += aw0 * tanh_ap(acc[nt][2]) + aw1 * tanh_ap(acc[nt][3]);
        }
        p0 += __shfl_xor_sync(0xffffffffu, p0, 1);
        p0 += __shfl_xor_sync(0xffffffffu, p0, 2);
        p1 += __shfl_xor_sync(0xffffffffu, p1, 1);
        p1 += __shfl_xor_sync(0xffffffffu, p1, 2);
        if (tig == 0) {
            spart[wn * TILE + rlo] = p0;
            spart[wn * TILE + rhi] = p1;
        }

        // ---- 2. T(t) was issued a full iteration ago → epilogue ----
        cp_wait1();                     // T(t) retired; X(t+1) may pend
        __syncthreads();                // spart + stis[buf] visible
        float* ts = stis + buf * TILE * DIM;
        #pragma unroll
        for (int j = 0; j < 4; j++) {
            int i = tid + j * 256;
            int r = i >> 5, c = i & 31;
            int row = base + r;
            if (row >= n_cell) continue;
            float s = spart[r] + spart[TILE + r]
                    + spart[2 * TILE + r] + spart[3 * TILE + r];
            float gg = __fdividef(1.f, 1.f + __expf(-s));
            float4 xv = *(const float4*)&bx[r * SXS + c * 4];
            float4 tv = *(const float4*)&ts[r * DIM + c * 4];
            float4 o;
            o.x = fmaf(tv.x, gg, xv.x);
            o.y = fmaf(tv.y, gg, xv.y);
            o.z = fmaf(tv.z, gg, xv.z);
            o.w = fmaf(tv.w, gg, xv.w);
            ((float4*)out)[(size_t)row * 32 + c] = o;
        }

        // ---- 3. X(t+1)+ids also issued a full iteration ago → refill ----
        cp_wait0();                     // X(t+1)+ids(t+1) resident
        __syncthreads();                // stid(t+1) visible; bx/ts free
        if (t + g < ntiles) issue_t(t + g, buf ^ 1);
        cp_commit();                    // [T(t+1)]
        if (t + 2 * g < ntiles) issue_x(t + 2 * g, buf);
        cp_commit();                    // [T(t+1), X(t+2)]
    }
}

// ---------------------------------------------------------------------------
extern "C" void kernel_launch(void* const* d_in, const int* in_sizes, int n_in,
                              void* d_out, int out_size) {
    const float* cellf   = (const float*)d_in[0];
    const float* tissuef = (const float*)d_in[1];
    const int*   c2t     = (const int*)d_in[2];
    const float* Wt      = (const float*)d_in[3];
    const float* bt      = (const float*)d_in[4];
    const float* Wc      = (const float*)d_in[5];
    const float* bc      = (const float*)d_in[6];
    const float* attnw   = (const float*)d_in[7];
    float* out = (float*)d_out;

    int n_cell   = in_sizes[0] / DIM;
    int n_tissue = in_sizes[1] / DIM;
    int ntiles   = (n_cell + TILE - 1) / TILE;

    tissue_proj_kernel<<<(n_tissue + 15) / 16, 256>>>(tissuef, Wt, bt, bc, n_tissue);

    int dev = 0, sms = 148;
    cudaGetDevice(&dev);
    cudaDeviceGetAttribute(&sms, cudaDevAttrMultiProcessorCount, dev);

    size_t shmem_bytes =
        (size_t)(2 * TILE * SXS) * 4        // X buffers (aliased Wc staging)
        + (size_t)(2 * TILE * DIM) * 4      // 2 tissue stages
        + (2 * TILE) * 4                    // stid
        + (4 * TILE) * 4                    // spart
        + 64 * 4;                           // sattn
    cudaFuncSetAttribute(fuse_kernel,
                         cudaFuncAttributeMaxDynamicSharedMemorySize,
                         (int)shmem_bytes);
    int grid = 2 * sms;
    if (grid > ntiles) grid = ntiles;
    fuse_kernel<<<grid, 256, shmem_bytes>>>(cellf, tissuef, c2t, Wc, attnw,
                                            out, n_cell, ntiles);
}

// round 16
// speedup vs baseline: 1.0095x; 1.0095x over previous
#include <cuda_runtime.h>
#include <cstdint>

#define DIM 128
#define HID 64
#define MAX_TISSUE 4096
#define TILE 64
#define SXS 132  // padded float stride, X tile
#define SWS 132  // padded float stride, Wc staging (tf32 bits)

// scratch: projected tissue keys (+ both biases folded in)
__device__ float g_tkb[MAX_TISSUE * HID];

// ---------------------------------------------------------------------------
// Kernel A: tkb[t][h] = bt[h] + bc[h] + sum_d Wt[h][d] * tissue[t][d]
// ---------------------------------------------------------------------------
__global__ void tissue_proj_kernel(const float* __restrict__ tissue,
                                   const float* __restrict__ Wt,
                                   const float* __restrict__ bt,
                                   const float* __restrict__ bc,
                                   int n_tissue) {
    __shared__ float st[16][DIM];
    __shared__ float swt[HID][DIM + 4];
    int tid = threadIdx.x;
    int t0 = blockIdx.x * 16;

    for (int i = tid; i < HID * (DIM / 4); i += 256) {
        int h = i >> 5, c = i & 31;
        float4 v = ((const float4*)Wt)[h * 32 + c];
        *(float4*)&swt[h][c * 4] = v;
    }
    for (int i = tid; i < 16 * 32; i += 256) {
        int r = i >> 5, c = i & 31;
        float4 v = make_float4(0.f, 0.f, 0.f, 0.f);
        if (t0 + r < n_tissue) v = ((const float4*)tissue)[(size_t)(t0 + r) * 32 + c];
        *(float4*)&st[r][c * 4] = v;
    }
    __syncthreads();

    #pragma unroll
    for (int j = 0; j < 4; j++) {
        int o = tid + j * 256;
        int tl = o >> 6, h = o & 63;
        if (t0 + tl >= n_tissue) continue;
        float acc = bt[h] + bc[h];
        #pragma unroll 8
        for (int c = 0; c < 32; c++) {
            float4 w = *(const float4*)&swt[h][c * 4];
            float4 x = *(const float4*)&st[tl][c * 4];
            acc += w.x * x.x + w.y * x.y + w.z * x.z + w.w * x.w;
        }
        g_tkb[(size_t)(t0 + tl) * HID + h] = acc;
    }
}

// ---------------------------------------------------------------------------
__device__ __forceinline__ unsigned f2tf32(float x) {
    unsigned r;
    asm("cvt.rna.tf32.f32 %0, %1;" : "=r"(r) : "f"(x));
    return r;
}
__device__ __forceinline__ float tanh_ap(float x) {
    float y;
    asm("tanh.approx.f32 %0, %1;" : "=f"(y) : "f"(x));
    return y;
}
__device__ __forceinline__ void cp_async16(void* sdst, const void* gsrc, bool pred) {
    unsigned s = (unsigned)__cvta_generic_to_shared(sdst);
    int sz = pred ? 16 : 0;
    asm volatile("cp.async.cg.shared.global [%0], [%1], 16, %2;\n"
                 :: "r"(s), "l"(gsrc), "r"(sz));
}
__device__ __forceinline__ void cp_async4(void* sdst, const void* gsrc, bool pred) {
    unsigned s = (unsigned)__cvta_generic_to_shared(sdst);
    int sz = pred ? 4 : 0;
    asm volatile("cp.async.ca.shared.global [%0], [%1], 4, %2;\n"
                 :: "r"(s), "l"(gsrc), "r"(sz));
}
__device__ __forceinline__ void cp_commit() {
    asm volatile("cp.async.commit_group;\n" ::: "memory");
}
__device__ __forceinline__ void cp_wait0() {
    asm volatile("cp.async.wait_group 0;\n" ::: "memory");
}
__device__ __forceinline__ void cp_wait1() {
    asm volatile("cp.async.wait_group 1;\n" ::: "memory");
}
__device__ __forceinline__ void ldm_x4(unsigned* r, unsigned saddr) {
    asm volatile("ldmatrix.sync.aligned.m8n8.x4.shared.b16 {%0,%1,%2,%3}, [%4];"
                 : "=r"(r[0]), "=r"(r[1]), "=r"(r[2]), "=r"(r[3])
                 : "r"(saddr));
}

extern __shared__ float smem[];

// ---------------------------------------------------------------------------
// Kernel B: persistent; 64-row tiles; 2 CTAs/SM; B register-resident;
// tissue gather staged via cp.async (R13 schedule). Each m-warp handles TWO
// m16 tiles -> 4 independent mma chains. Warp grid: 2 m-warps x 4 n-quarters.
// ---------------------------------------------------------------------------
__global__ __launch_bounds__(256, 2)
void fuse_kernel(const float* __restrict__ cellf,
                 const float* __restrict__ tissuef,
                 const int* __restrict__ c2t,
                 const float* __restrict__ Wc,
                 const float* __restrict__ attnw,
                 float* __restrict__ out,
                 int n_cell, int ntiles) {
    float*    sx    = smem;                      // 2 X buffers, 64*132 each
    unsigned* swc   = (unsigned*)smem;           // ALIAS: Wc staging (prologue)
    float*    stis  = smem + 2 * TILE * SXS;     // tissue stage, 64*128
    int*      stid  = (int*)(stis + TILE * DIM); // 2 buffers, 64 each
    float*    spart = (float*)(stid + 2 * TILE); // 4 * 64 partials
    float*    sattn = spart + 4 * TILE;          // 64

    int tid = threadIdx.x;
    int wid = tid >> 5, lane = tid & 31;
    int gid = lane >> 2, tig = lane & 3;
    int wm = wid & 1, wn = wid >> 1;     // 2 m-warps x 4 n-quarters
    int h0 = wn * 16;

    int lml = lane & 7, lmm = lane >> 3;
    unsigned sx_u = (unsigned)__cvta_generic_to_shared(sx);
    unsigned a_lane = ((unsigned)(((lmm & 1) * 8 + lml) * SXS + (lmm >> 1) * 4)) * 4u;
    unsigned b_off = sx_u + ((unsigned)((h0 + lml) * SWS + lmm * 4)) * 4u;

    // ---- prologue: stage Wc tf32 (aliased), extract B fragments to regs ----
    for (int i = tid; i < 64 * 32; i += 256) {
        int r = i >> 5, c = i & 31;
        float4 v = ((const float4*)Wc)[r * 32 + c];
        uint4 w;
        w.x = f2tf32(v.x); w.y = f2tf32(v.y); w.z = f2tf32(v.z); w.w = f2tf32(v.w);
        *(uint4*)&swc[r * SWS + c * 4] = w;
    }
    if (tid < 64) sattn[tid] = attnw[tid];
    __syncthreads();

    unsigned breg[2][8][4];   // loop-invariant B fragments (64 regs)
    #pragma unroll
    for (int nt = 0; nt < 2; nt++)
        #pragma unroll
        for (int p = 0; p < 8; p++)
            ldm_x4(breg[nt][p],
                   b_off + (unsigned)(nt * 8 * SWS) * 4u + (unsigned)(p * 64));
    __syncthreads();          // Wc staging region reusable as X buffers

    // ---- helpers ----
    auto issue_x = [&](int t, int buf) {
        float* dst = sx + buf * TILE * SXS;
        int base = t * TILE;
        #pragma unroll
        for (int j = 0; j < 8; j++) {
            int i = tid + j * 256;
            int r = i >> 5, c = i & 31;
            int row = base + r;
            bool ok = row < n_cell;
            int rowc = ok ? row : (n_cell - 1);
            cp_async16(&dst[r * SXS + c * 4],
                       cellf + (size_t)rowc * DIM + c * 4, ok);
        }
        if (tid < TILE) {
            int row = base + tid;
            bool ok = row < n_cell;
            int rowc = ok ? row : 0;
            cp_async4(&stid[buf * TILE + tid], c2t + rowc, ok);
        }
    };

    int t0 = blockIdx.x;
    if (t0 < ntiles) issue_x(t0, 0);
    cp_commit();                        // pending: {X(t0)}

    int it = 0;
    for (int t = t0; t < ntiles; t += gridDim.x, it++) {
        int buf = it & 1;
        cp_wait0();                     // X(t) + ids(t) resident
        __syncthreads();                // stid visible; buffers safe

        int base = t * TILE;
        int* bt_ = stid + buf * TILE;

        // ---- stage tissue rows for tile t (overlaps with mma below) ----
        #pragma unroll
        for (int j = 0; j < 8; j++) {
            int i = tid + j * 256;
            int r = i >> 5, c = i & 31;
            bool ok = (base + r) < n_cell;
            int tt = bt_[r] & (MAX_TISSUE - 1);
            cp_async16(&stis[r * DIM + c * 4],
                       tissuef + (size_t)tt * DIM + c * 4, ok);
        }
        cp_commit();                    // T(t)   [older]

        int tn = t + gridDim.x;
        if (tn < ntiles) issue_x(tn, buf ^ 1);
        cp_commit();                    // X(t+1) [newest]

        float* bx = sx + buf * TILE * SXS;
        unsigned xbase = sx_u + (unsigned)(buf * TILE * SXS) * 4u;

        // ---- init 4 accumulator chains from gathered tissue keys ----
        float acc[2][2][4];             // [mt][nt][frag]
        #pragma unroll
        for (int mt = 0; mt < 2; mt++) {
            int m0 = wm * 32 + mt * 16;
            int tlo = bt_[m0 + gid] & (MAX_TISSUE - 1);
            int thi = bt_[m0 + gid + 8] & (MAX_TISSUE - 1);
            const float2* klo = (const float2*)&g_tkb[(size_t)tlo * HID];
            const float2* khi = (const float2*)&g_tkb[(size_t)thi * HID];
            #pragma unroll
            for (int nt = 0; nt < 2; nt++) {
                float2 a = klo[wn * 8 + nt * 4 + tig];
                float2 b = khi[wn * 8 + nt * 4 + tig];
                acc[mt][nt][0] = a.x; acc[mt][nt][1] = a.y;
                acc[mt][nt][2] = b.x; acc[mt][nt][3] = b.y;
            }
        }

        // ---- Q += X @ Wc^T : 4 independent chains per warp ----
        unsigned ab0 = xbase + (unsigned)((wm * 32) * SXS) * 4u + a_lane;
        unsigned ab1 = ab0 + (unsigned)(16 * SXS) * 4u;
        #pragma unroll
        for (int p = 0; p < 8; p++) {
            unsigned a00[4], a01[4], a10[4], a11[4];
            ldm_x4(a00, ab0 + (unsigned)(p * 64));        // mt0, kk=2p
            ldm_x4(a01, ab0 + (unsigned)(p * 64 + 32));   // mt0, kk=2p+1
            ldm_x4(a10, ab1 + (unsigned)(p * 64));        // mt1, kk=2p
            ldm_x4(a11, ab1 + (unsigned)(p * 64 + 32));   // mt1, kk=2p+1
            #pragma unroll
            for (int nt = 0; nt < 2; nt++) {
                asm volatile(
                    "mma.sync.aligned.m16n8k8.row.col.f32.tf32.tf32.f32 "
                    "{%0,%1,%2,%3}, {%4,%5,%6,%7}, {%8,%9}, {%0,%1,%2,%3};\n"
                    : "+f"(acc[0][nt][0]), "+f"(acc[0][nt][1]),
                      "+f"(acc[0][nt][2]), "+f"(acc[0][nt][3])
                    : "r"(a00[0]), "r"(a00[1]), "r"(a00[2]), "r"(a00[3]),
                      "r"(breg[nt][p][0]), "r"(breg[nt][p][1]));
                asm volatile(
                    "mma.sync.aligned.m16n8k8.row.col.f32.tf32.tf32.f32 "
                    "{%0,%1,%2,%3}, {%4,%5,%6,%7}, {%8,%9}, {%0,%1,%2,%3};\n"
                    : "+f"(acc[1][nt][0]), "+f"(acc[1][nt][1]),
                      "+f"(acc[1][nt][2]), "+f"(acc[1][nt][3])
                    : "r"(a10[0]), "r"(a10[1]), "r"(a10[2]), "r"(a10[3]),
                      "r"(breg[nt][p][0]), "r"(breg[nt][p][1]));
                asm volatile(
                    "mma.sync.aligned.m16n8k8.row.col.f32.tf32.tf32.f32 "
                    "{%0,%1,%2,%3}, {%4,%5,%6,%7}, {%8,%9}, {%0,%1,%2,%3};\n"
                    : "+f"(acc[0][nt][0]), "+f"(acc[0][nt][1]),
                      "+f"(acc[0][nt][2]), "+f"(acc[0][nt][3])
                    : "r"(a01[0]), "r"(a01[1]), "r"(a01[2]), "r"(a01[3]),
                      "r"(breg[nt][p][2]), "r"(breg[nt][p][3]));
                asm volatile(
                    "mma.sync.aligned.m16n8k8.row.col.f32.tf32.tf32.f32 "
                    "{%0,%1,%2,%3}, {%4,%5,%6,%7}, {%8,%9}, {%0,%1,%2,%3};\n"
                    : "+f"(acc[1][nt][0]), "+f"(acc[1][nt][1]),
                      "+f"(acc[1][nt][2]), "+f"(acc[1][nt][3])
                    : "r"(a11[0]), "r"(a11[1]), "r"(a11[2]), "r"(a11[3]),
                      "r"(breg[nt][p][2]), "r"(breg[nt][p][3]));
            }
        }

        // ---- partial scores over this warp's 16 cols, both m-tiles ----
        #pragma unroll
        for (int mt = 0; mt < 2; mt++) {
            float p0 = 0.f, p1 = 0.f;
            #pragma unroll
            for (int nt = 0; nt < 2; nt++) {
                float aw0 = sattn[h0 + nt * 8 + tig * 2];
                float aw1 = sattn[h0 + nt * 8 + tig * 2 + 1];
                p0 += aw0 * tanh_ap(acc[mt][nt][0]) + aw1 * tanh_ap(acc[mt][nt][1]);
                p1 += aw0 * tanh_ap(acc[mt][nt][2]) + aw1 * tanh_ap(acc[mt][nt][3]);
            }
            p0 += __shfl_xor_sync(0xffffffffu, p0, 1);
            p0 += __shfl_xor_sync(0xffffffffu, p0, 2);
            p1 += __shfl_xor_sync(0xffffffffu, p1, 1);
            p1 += __shfl_xor_sync(0xffffffffu, p1, 2);
            if (tig == 0) {
                int m0 = wm * 32 + mt * 16;
                spart[wn * TILE + m0 + gid] = p0;
                spart[wn * TILE + m0 + gid + 8] = p1;
            }
        }

        cp_wait1();                     // T(t) retired (X(t+1) may pend)
        __syncthreads();                // spart + stis visible

        // ---- epilogue: gate inline; out = x + tissue_staged * gate ----
        #pragma unroll
        for (int j = 0; j < 8; j++) {
            int i = tid + j * 256;
            int r = i >> 5, c = i & 31;
            int row = base + r;
            if (row >= n_cell) continue;
            float s = spart[r] + spart[TILE + r]
                    + spart[2 * TILE + r] + spart[3 * TILE + r];
            float gg = __fdividef(1.f, 1.f + __expf(-s));
            float4 xv = *(const float4*)&bx[r * SXS + c * 4];
            float4 tv = *(const float4*)&stis[r * DIM + c * 4];
            float4 o;
            o.x = fmaf(tv.x, gg, xv.x);
            o.y = fmaf(tv.y, gg, xv.y);
            o.z = fmaf(tv.z, gg, xv.z);
            o.w = fmaf(tv.w, gg, xv.w);
            ((float4*)out)[(size_t)row * 32 + c] = o;
        }
        // next iteration's cp_wait0 + __syncthreads fences buffer reuse
    }
}

// ---------------------------------------------------------------------------
extern "C" void kernel_launch(void* const* d_in, const int* in_sizes, int n_in,
                              void* d_out, int out_size) {
    const float* cellf   = (const float*)d_in[0];
    const float* tissuef = (const float*)d_in[1];
    const int*   c2t     = (const int*)d_in[2];
    const float* Wt      = (const float*)d_in[3];
    const float* bt      = (const float*)d_in[4];
    const float* Wc      = (const float*)d_in[5];
    const float* bc      = (const float*)d_in[6];
    const float* attnw   = (const float*)d_in[7];
    float* out = (float*)d_out;

    int n_cell   = in_sizes[0] / DIM;
    int n_tissue = in_sizes[1] / DIM;
    int ntiles   = (n_cell + TILE - 1) / TILE;

    tissue_proj_kernel<<<(n_tissue + 15) / 16, 256>>>(tissuef, Wt, bt, bc, n_tissue);

    int dev = 0, sms = 148;
    cudaGetDevice(&dev);
    cudaDeviceGetAttribute(&sms, cudaDevAttrMultiProcessorCount, dev);

    size_t shmem_bytes =
        (size_t)(2 * TILE * SXS) * 4    // X buffers (aliased Wc staging)
        + (size_t)(TILE * DIM) * 4      // tissue stage
        + (2 * TILE) * 4                // stid
        + (4 * TILE) * 4                // spart
        + 64 * 4;                       // sattn
    cudaFuncSetAttribute(fuse_kernel,
                         cudaFuncAttributeMaxDynamicSharedMemorySize,
                         (int)shmem_bytes);
    int grid = 2 * sms;
    if (grid > ntiles) grid = ntiles;
    fuse_kernel<<<grid, 256, shmem_bytes>>>(cellf, tissuef, c2t, Wc, attnw,
                                            out, n_cell, ntiles);
}